// round 11
// baseline (speedup 1.0000x reference)
#include <cuda_runtime.h>
#include <cuda_fp16.h>
#include <math.h>

// FARGAN vocoder on GB300.
// Kernel 0 (pack): convert the four big streamed weight matrices to fp16 scratch.
// Kernel 1 (cond): parallel conditioning prepass (fp32).
// Kernel 2 (recur): serial recurrence, 1 CTA x 512 thr per batch element.
//   Big matvecs stream fp16 weights (fp32 accumulate); small weights fp32 in smem.

#define NT  512   // recurrence kernel block
#define NTC 256   // conditioning kernel block

namespace {
constexpr int S      = 64;
constexpr int L      = 512;
constexpr int F      = 193;
constexpr int BATCH  = 64;
constexpr int FRAMES = 100;
constexpr int NSUB   = 4;
constexpr int OUT_PER_B = FRAMES * NSUB * S;  // 25600

constexpr int TFRM   = 20;
constexpr int NTILES = FRAMES / TFRM;

// fp16 scratch offsets (in halves); all row strides multiple of 8 (uint4 aligned)
constexpr int FW_COLS = 392;                       // 388 padded to 392
constexpr int OFF_FW  = 0;                         // 64 x 392
constexpr int OFF_IH  = OFF_FW + 64 * FW_COLS;     // 3 x (192 x 128)
constexpr int OFF_HH  = OFF_IH + 3 * 192 * 128;    // 3 x (192 x 64)
constexpr int OFF_SD  = OFF_HH + 3 * 192 * 64;     // 128 x 320
constexpr int WH_TOTAL = OFF_SD + 128 * 320;       // 176,640 halves

// padded smem weight row strides for fp32 small matrices, in float4 units
constexpr int FWG4 = 17;   // 64/4 + 1
constexpr int G4   = 17;
constexpr int OUT4 = 33;   // 128/4 + 1
constexpr int SG4  = 33;

constexpr int W_FWG_F4 = 64 * FWG4;
constexpr int W_G_F4   = 64 * G4;
constexpr int W_OUT_F4 = 64 * OUT4;
constexpr int W_SG_F4  = 128 * SG4;

struct SmemAct {
    float ring[512];
    float c[512];
    float vin[392];    // [feat2s 128 | prev_sub 64 | lookback 68 | sfw 128 | pad 4 (zero)]
    float fwt[64];
    float gi[192];
    float gh[192];
    float xg[128];
    float skip[320];   // [o1 | o2 | o3 | fw | prev_sub]
    float sd[128];
    float sd2[128];
    float s1[64], s2[64], s3[64];
    float sfw[128];
};

constexpr size_t SMEM_BYTES =
    sizeof(SmemAct) + (size_t)(W_FWG_F4 + 3 * W_G_F4 + W_OUT_F4 + W_SG_F4) * 16;

struct CondSmem {
    float x [TFRM][256];
    float c1[TFRM][256];
    float c2[TFRM][256];
};
constexpr size_t COND_SMEM_BYTES = sizeof(CondSmem);
}

__device__ float  g_cond[(size_t)BATCH * FRAMES * 512];
__device__ __half g_wh[WH_TOTAL];

__device__ __forceinline__ float sigm(float v) {
    return 1.0f / (1.0f + __expf(-v));
}

// ---------------------------------------------------------------------------
// Kernel 0: pack big weights to fp16 scratch.
// ---------------------------------------------------------------------------
__global__ void pack_kernel(const float* __restrict__ Wfw,
                            const float* __restrict__ Wih1,
                            const float* __restrict__ Wih2,
                            const float* __restrict__ Wih3,
                            const float* __restrict__ Whh1,
                            const float* __restrict__ Whh2,
                            const float* __restrict__ Whh3,
                            const float* __restrict__ Wsd) {
    const int tid = blockIdx.x * blockDim.x + threadIdx.x;
    const int nthr = gridDim.x * blockDim.x;
    // Wfw: 64 x 388 -> 64 x 392 (zero pad)
    for (int i = tid; i < 64 * FW_COLS; i += nthr) {
        int r = i / FW_COLS, c = i - r * FW_COLS;
        g_wh[OFF_FW + i] = __float2half(c < 388 ? Wfw[r * 388 + c] : 0.f);
    }
    const float* ih[3] = { Wih1, Wih2, Wih3 };
    for (int g = 0; g < 3; g++)
        for (int i = tid; i < 192 * 128; i += nthr)
            g_wh[OFF_IH + g * 192 * 128 + i] = __float2half(ih[g][i]);
    const float* hh[3] = { Whh1, Whh2, Whh3 };
    for (int g = 0; g < 3; g++)
        for (int i = tid; i < 192 * 64; i += nthr)
            g_wh[OFF_HH + g * 192 * 64 + i] = __float2half(hh[g][i]);
    for (int i = tid; i < 128 * 320; i += nthr)
        g_wh[OFF_SD + i] = __float2half(Wsd[i]);
}

// ---------------------------------------------------------------------------
// Kernel 1: conditioning prepass. grid = (BATCH, NTILES), block = 256.
// ---------------------------------------------------------------------------
__global__ void __launch_bounds__(NTC, 1)
cond_kernel(const float* __restrict__ features,
            const float* __restrict__ gfeat,
            const float* __restrict__ Wc1,
            const float* __restrict__ Wc2,
            const float* __restrict__ Wc3) {
    extern __shared__ char raw[];
    CondSmem& cs = *reinterpret_cast<CondSmem*>(raw);
    const int b   = blockIdx.x;
    const int t0  = blockIdx.y * TFRM;
    const int tid = threadIdx.x;
    const float* featb = features + (long)b * F * FRAMES;

    for (int idx = tid; idx < TFRM * 256; idx += NTC) {
        int t = idx >> 8;
        int i = idx & 255;
        cs.x[t][i] = (i < 192) ? featb[i * FRAMES + (t0 + t)]
                               : gfeat[b * 64 + (i - 192)];
    }
    __syncthreads();

    {
        const float4* __restrict__ W4 = reinterpret_cast<const float4*>(Wc1) + tid * 64;
        float acc[TFRM];
        #pragma unroll
        for (int t = 0; t < TFRM; t++) acc[t] = 0.f;
        #pragma unroll 4
        for (int j = 0; j < 64; j++) {
            float4 w = W4[j];
            #pragma unroll
            for (int t = 0; t < TFRM; t++) {
                const float4 a = reinterpret_cast<const float4*>(cs.x[t])[j];
                acc[t] += w.x * a.x + w.y * a.y + w.z * a.z + w.w * a.w;
            }
        }
        #pragma unroll
        for (int t = 0; t < TFRM; t++) cs.c1[t][tid] = tanhf(acc[t]);
    }
    __syncthreads();

    {
        const float4* __restrict__ W4 = reinterpret_cast<const float4*>(Wc2) + tid * 64;
        float acc[TFRM];
        #pragma unroll
        for (int t = 0; t < TFRM; t++) acc[t] = 0.f;
        #pragma unroll 4
        for (int j = 0; j < 64; j++) {
            float4 w = W4[j];
            #pragma unroll
            for (int t = 0; t < TFRM; t++) {
                const float4 a = reinterpret_cast<const float4*>(cs.c1[t])[j];
                acc[t] += w.x * a.x + w.y * a.y + w.z * a.z + w.w * a.w;
            }
        }
        #pragma unroll
        for (int t = 0; t < TFRM; t++) cs.c2[t][tid] = tanhf(acc[t]);
    }
    __syncthreads();

    {
        const float4* __restrict__ W4a = reinterpret_cast<const float4*>(Wc3) + tid * 64;
        const float4* __restrict__ W4b = W4a + 256 * 64;
        float acc0[TFRM], acc1[TFRM];
        #pragma unroll
        for (int t = 0; t < TFRM; t++) { acc0[t] = 0.f; acc1[t] = 0.f; }
        #pragma unroll 2
        for (int j = 0; j < 64; j++) {
            float4 wa = W4a[j];
            float4 wb = W4b[j];
            #pragma unroll
            for (int t = 0; t < TFRM; t++) {
                const float4 a = reinterpret_cast<const float4*>(cs.c2[t])[j];
                acc0[t] += wa.x * a.x + wa.y * a.y + wa.z * a.z + wa.w * a.w;
                acc1[t] += wb.x * a.x + wb.y * a.y + wb.z * a.z + wb.w * a.w;
            }
        }
        #pragma unroll
        for (int t = 0; t < TFRM; t++) {
            float* dst = g_cond + ((long)b * FRAMES + (t0 + t)) * 512;
            dst[tid]       = tanhf(acc0[t]);
            dst[tid + 256] = tanhf(acc1[t]);
        }
    }
}

// ---------------------------------------------------------------------------
// fp32 matvec (smem weights), block = NT.
// ---------------------------------------------------------------------------
template<int O, int I, int P, int STR4, class Epi>
__device__ __forceinline__ void matvec(const float* __restrict__ W,
                                       const float* __restrict__ v,
                                       int tid, Epi epi) {
    constexpr int NV    = I / 4;
    constexpr int RPP   = NT / P;
    constexpr int NPASS = (O + RPP - 1) / RPP;
    constexpr int NITER = (NV + P - 1) / P;
    const float4* __restrict__ W4 = reinterpret_cast<const float4*>(W);
    const float4* __restrict__ v4 = reinterpret_cast<const float4*>(v);
    const int part  = tid & (P - 1);
    const int rbase = tid / P;

    #pragma unroll
    for (int p = 0; p < NPASS; p++) {
        const int row = p * RPP + rbase;
        if ((O % (NT / P) != 0) && row >= O) break;
        const float4* __restrict__ wr = W4 + row * STR4;
        float4 acc = make_float4(0.f, 0.f, 0.f, 0.f);
        #pragma unroll
        for (int it = 0; it < NITER; it++) {
            const int j = part + it * P;
            if ((NV % P == 0) || (j < NV)) {
                float4 w = wr[j];
                float4 a = v4[j];
                acc.x += w.x * a.x;
                acc.y += w.y * a.y;
                acc.z += w.z * a.z;
                acc.w += w.w * a.w;
            }
        }
        float s = (acc.x + acc.y) + (acc.z + acc.w);
        #pragma unroll
        for (int m = 1; m < P; m <<= 1)
            s += __shfl_xor_sync(0xffffffffu, s, m);
        if (part == 0) epi(row, s);
    }
}

// ---------------------------------------------------------------------------
// fp16-weight matvec (gmem fp16 weights, fp32 smem vector, fp32 accumulate).
// IH = padded row length in halves (multiple of 8). Valid v length == IH
// (vector must be zero-padded to IH if logical I < IH).
// ---------------------------------------------------------------------------
template<int O, int IH, int P, class Epi>
__device__ __forceinline__ void matvec_h(const __half* __restrict__ W,
                                         const float* __restrict__ v,
                                         int tid, Epi epi) {
    constexpr int NVH   = IH / 8;            // uint4 (8 halves) per row
    constexpr int RPP   = NT / P;
    constexpr int NPASS = (O + RPP - 1) / RPP;
    constexpr int NITER = (NVH + P - 1) / P;
    const uint4*  __restrict__ W8 = reinterpret_cast<const uint4*>(W);
    const float4* __restrict__ v4 = reinterpret_cast<const float4*>(v);
    const int part  = tid & (P - 1);
    const int rbase = tid / P;

    #pragma unroll
    for (int p = 0; p < NPASS; p++) {
        const int row = p * RPP + rbase;
        if ((O % (NT / P) != 0) && row >= O) break;
        const uint4* __restrict__ wr = W8 + row * NVH;
        float acc = 0.f;
        #pragma unroll
        for (int it = 0; it < NITER; it++) {
            const int j = part + it * P;
            if ((NVH % P == 0) || (j < NVH)) {
                uint4 wv = wr[j];
                const __half2* wh = reinterpret_cast<const __half2*>(&wv);
                float2 w0 = __half22float2(wh[0]);
                float2 w1 = __half22float2(wh[1]);
                float2 w2 = __half22float2(wh[2]);
                float2 w3 = __half22float2(wh[3]);
                float4 a0 = v4[2 * j];
                float4 a1 = v4[2 * j + 1];
                acc += w0.x * a0.x + w0.y * a0.y + w1.x * a0.z + w1.y * a0.w
                     + w2.x * a1.x + w2.y * a1.y + w3.x * a1.z + w3.y * a1.w;
            }
        }
        #pragma unroll
        for (int m = 1; m < P; m <<= 1)
            acc += __shfl_xor_sync(0xffffffffu, acc, m);
        if (part == 0) epi(row, acc);
    }
}

// copy (O x I) fp32 gmem matrix into smem with padded row stride PAD4 (f4 units)
template<int O, int I, int PAD4>
__device__ __forceinline__ void stage(const float* __restrict__ W,
                                      float4* __restrict__ dst, int tid) {
    constexpr int NV = I / 4;
    const float4* __restrict__ src = reinterpret_cast<const float4*>(W);
    for (int k = tid; k < O * NV; k += NT) {
        int r = k / NV;
        int j = k - r * NV;
        dst[r * PAD4 + j] = src[k];
    }
}

// ---------------------------------------------------------------------------
// Kernel 2: serial recurrence. grid = BATCH, block = 512.
// ---------------------------------------------------------------------------
__global__ void __launch_bounds__(NT, 1)
fargan_kernel(const float* __restrict__ features,
              const float* __restrict__ prev0,
              const float* __restrict__ Wfwg, const float* __restrict__ Wg1,
              const float* __restrict__ Wg2,  const float* __restrict__ Wg3,
              const float* __restrict__ Wsg,  const float* __restrict__ Wout,
              float* __restrict__ out) {
    extern __shared__ char raw[];
    SmemAct& sm = *reinterpret_cast<SmemAct*>(raw);
    float4* wbase = reinterpret_cast<float4*>(raw + sizeof(SmemAct));
    float4* w_fwg = wbase;
    float4* w_g1  = w_fwg + W_FWG_F4;
    float4* w_g2  = w_g1 + W_G_F4;
    float4* w_g3  = w_g2 + W_G_F4;
    float4* w_out = w_g3 + W_G_F4;
    float4* w_sg  = w_out + W_OUT_F4;

    const int b   = blockIdx.x;
    const int tid = threadIdx.x;

    stage<64, 64, FWG4>(Wfwg, w_fwg, tid);
    stage<64, 64, G4>  (Wg1,  w_g1,  tid);
    stage<64, 64, G4>  (Wg2,  w_g2,  tid);
    stage<64, 64, G4>  (Wg3,  w_g3,  tid);
    stage<64, 128, OUT4>(Wout, w_out, tid);
    stage<128, 128, SG4>(Wsg,  w_sg,  tid);

    for (int i = tid; i < 512; i += NT) sm.ring[i] = prev0[b * 512 + i];
    if (tid < 64) { sm.s1[tid] = 0.f; sm.s2[tid] = 0.f; sm.s3[tid] = 0.f; }
    if (tid < 128) sm.sfw[tid] = 0.f;
    if (tid < 4)  sm.vin[388 + tid] = 0.f;   // zero pad (stays zero)
    int head = 0;
    __syncthreads();

    const float* featb = features + (long)b * F * FRAMES;
    const float* condb = g_cond + (long)b * FRAMES * 512;
    float* outb = out + (long)b * OUT_PER_B;
    const float* wfwg_f = reinterpret_cast<const float*>(w_fwg);
    const float* wg_f[3] = { reinterpret_cast<const float*>(w_g1),
                             reinterpret_cast<const float*>(w_g2),
                             reinterpret_cast<const float*>(w_g3) };
    const float* wout_f = reinterpret_cast<const float*>(w_out);
    const float* wsg_f  = reinterpret_cast<const float*>(w_sg);
    float* st[3] = { sm.s1, sm.s2, sm.s3 };

    for (int t = 0; t < FRAMES; t++) {
        if (tid < 512) sm.c[tid] = condb[t * 512 + tid];
        const int period = __float2int_rn(featb[192 * FRAMES + t]);
        __syncthreads();

        for (int k = 0; k < NSUB; k++) {
            // ---- A: build vin, update sfw ----
            if (tid < 128) {
                float f = sm.c[tid * 4 + k];
                sm.vin[tid]       = f;
                sm.vin[260 + tid] = sm.sfw[tid];
                sm.sfw[tid]       = f;
            }
            if (tid >= 128 && tid < 192) {
                int i = tid - 128;
                float p = sm.ring[(head + 448 + i) & 511];
                sm.vin[128 + i]  = p;
                sm.xg[64 + i]    = p;
                sm.skip[256 + i] = p;
            }
            if (tid >= 192 && tid < 260) {
                int i = tid - 192;
                int idx = L - period + i - 2;
                if (idx >= L) idx -= period;
                sm.vin[192 + i] = sm.ring[(head + idx) & 511];
            }
            __syncthreads();

            // ---- B: fwt = tanh(Wfw @ vin)  (fp16 stream) ----
            matvec_h<64, FW_COLS, 8>(g_wh + OFF_FW, sm.vin, tid,
                [&](int r, float s) { sm.fwt[r] = tanhf(s); });
            __syncthreads();

            // ---- C: fw = fwt * sigm(Wfwg @ fwt)  (smem fp32) ----
            matvec<64, 64, 8, FWG4>(wfwg_f, sm.fwt, tid,
                [&](int r, float s) {
                    float fw = sm.fwt[r] * sigm(s);
                    sm.xg[r]         = fw;
                    sm.skip[192 + r] = fw;
                });
            __syncthreads();

            // ---- three GRU + GLU stages ----
            #pragma unroll
            for (int g = 0; g < 3; g++) {
                float* state = st[g];
                matvec_h<192, 128, 8>(g_wh + OFF_IH + g * 192 * 128, sm.xg, tid,
                    [&](int r, float s) { sm.gi[r] = s; });
                matvec_h<192, 64, 8>(g_wh + OFF_HH + g * 192 * 64, state, tid,
                    [&](int r, float s) { sm.gh[r] = s; });
                __syncthreads();
                if (tid < 64) {
                    float r = sigm(sm.gi[tid]        + sm.gh[tid]);
                    float z = sigm(sm.gi[64 + tid]   + sm.gh[64 + tid]);
                    float n = tanhf(sm.gi[128 + tid] + r * sm.gh[128 + tid]);
                    state[tid] = (1.0f - z) * n + z * state[tid];
                }
                __syncthreads();
                matvec<64, 64, 8, G4>(wg_f[g], state, tid,
                    [&](int r, float s) {
                        float o = state[r] * sigm(s);
                        sm.skip[g * 64 + r] = o;
                        sm.xg[r] = o;
                    });
                __syncthreads();
            }

            // ---- G: sd = tanh(Wsd @ skip)  (fp16 stream) ----
            matvec_h<128, 320, 8>(g_wh + OFF_SD, sm.skip, tid,
                [&](int r, float s) { sm.sd[r] = tanhf(s); });
            __syncthreads();

            // ---- H: sd2 = sd * sigm(Wsg @ sd)  (smem fp32) ----
            matvec<128, 128, 8, SG4>(wsg_f, sm.sd, tid,
                [&](int r, float s) { sm.sd2[r] = sm.sd[r] * sigm(s); });
            __syncthreads();

            // ---- I: out = tanh(Wout @ sd2); write ring + gmem ----
            matvec<64, 128, 8, OUT4>(wout_f, sm.sd2, tid,
                [&](int r, float s) {
                    float o = tanhf(s);
                    sm.ring[(head + r) & 511] = o;   // == new_head+448+r (mod 512)
                    outb[t * (NSUB * S) + k * S + r] = o;
                });
            __syncthreads();
            head = (head + 64) & 511;
        }
    }
}

extern "C" void kernel_launch(void* const* d_in, const int* in_sizes, int n_in,
                              void* d_out, int out_size) {
    (void)in_sizes; (void)n_in; (void)out_size;
    const float* features = (const float*)d_in[0];
    const float* gfeat    = (const float*)d_in[1];
    const float* prev0    = (const float*)d_in[2];
    const float* Wc1  = (const float*)d_in[3];
    const float* Wc2  = (const float*)d_in[4];
    const float* Wc3  = (const float*)d_in[5];
    const float* Wfw  = (const float*)d_in[6];
    const float* Wfwg = (const float*)d_in[7];
    const float* Wih1 = (const float*)d_in[8];
    const float* Whh1 = (const float*)d_in[9];
    const float* Wih2 = (const float*)d_in[10];
    const float* Whh2 = (const float*)d_in[11];
    const float* Wih3 = (const float*)d_in[12];
    const float* Whh3 = (const float*)d_in[13];
    const float* Wg1  = (const float*)d_in[14];
    const float* Wg2  = (const float*)d_in[15];
    const float* Wg3  = (const float*)d_in[16];
    const float* Wsg  = (const float*)d_in[17];
    const float* Wsd  = (const float*)d_in[18];
    const float* Wout = (const float*)d_in[19];

    cudaFuncSetAttribute(cond_kernel,
                         cudaFuncAttributeMaxDynamicSharedMemorySize,
                         (int)COND_SMEM_BYTES);
    cudaFuncSetAttribute(fargan_kernel,
                         cudaFuncAttributeMaxDynamicSharedMemorySize,
                         (int)SMEM_BYTES);

    pack_kernel<<<64, 256>>>(Wfw, Wih1, Wih2, Wih3, Whh1, Whh2, Whh3, Wsd);
    dim3 cgrid(BATCH, NTILES);
    cond_kernel<<<cgrid, NTC, COND_SMEM_BYTES>>>(features, gfeat, Wc1, Wc2, Wc3);
    fargan_kernel<<<BATCH, NT, SMEM_BYTES>>>(features, prev0,
                                             Wfwg, Wg1, Wg2, Wg3, Wsg, Wout,
                                             (float*)d_out);
}